// round 8
// baseline (speedup 1.0000x reference)
#include <cuda_runtime.h>
#include <cuda_fp16.h>
#include <cstdint>

// Problem constants
#define BATCH 512
#define INF   4096
#define OUTF  4096

// GEMM tiling: CTA 128x128, K-chunk 64 halves (128B rows). Warp grid 2(M) x 4(N).
#define TM 128
#define TN 128
#define KC 64                      // halves per K-chunk
#define ITERS (INF / KC)           // 64
#define STAGES 4
#define AS_STRIDE 72               // halves per smem row (64 + 8 pad) -> conflict-free LDSM
#define TILE_HALVES (128 * AS_STRIDE)            // 9216 halves = 18432 B
#define STAGE_BYTES (2 * TILE_HALVES * 2)        // A + B = 36864 B
#define SMEM_BYTES (STAGES * STAGE_BYTES)        // 147456 B

#define GEMM_CTAS 128
#define PROD_CTAS 20
#define ROWS_PER_PROD 205          // ceil(4096/20); last producer gets 201

// Scratch + handshake (device globals are the sanctioned scratch mechanism)
__device__ __half g_W[(size_t)OUTF * INF];   // dequantized weight, fp16 (32 MB)
__device__ __half g_x[(size_t)BATCH * INF];  // x, fp16 (4 MB)
__device__ int    g_flag[ITERS];             // per-chunk producer counters

// ---------------- PTX helpers (plain-sm_103 legal) ----------------
__device__ __forceinline__ uint32_t smem_u32(const void* p) {
    uint32_t a;
    asm("{ .reg .u64 t; cvta.to.shared.u64 t, %1; cvt.u32.u64 %0, t; }" : "=r"(a) : "l"(p));
    return a;
}

#define CP_ASYNC16(dst_smem, src_gmem) \
    asm volatile("cp.async.cg.shared.global [%0], [%1], 16;" \
                 :: "r"((uint32_t)(dst_smem)), "l"(src_gmem) : "memory")
#define CP_COMMIT() asm volatile("cp.async.commit_group;" ::: "memory")
#define CP_WAIT(n)  asm volatile("cp.async.wait_group %0;" :: "n"(n) : "memory")

#define LDSM_X4(r0, r1, r2, r3, addr) \
    asm volatile("ldmatrix.sync.aligned.m8n8.x4.shared.b16 {%0,%1,%2,%3}, [%4];" \
                 : "=r"(r0), "=r"(r1), "=r"(r2), "=r"(r3) : "r"(addr))

// mma.sync m16n8k16 f16 with f32 accumulate (sm_80 baseline)
#define MMA_F16(d, a, b) \
    asm volatile( \
        "mma.sync.aligned.m16n8k16.row.col.f32.f16.f16.f32 " \
        "{%0,%1,%2,%3}, {%4,%5,%6,%7}, {%8,%9}, {%0,%1,%2,%3};" \
        : "+f"((d)[0]), "+f"((d)[1]), "+f"((d)[2]), "+f"((d)[3]) \
        : "r"((a)[0]), "r"((a)[1]), "r"((a)[2]), "r"((a)[3]), \
          "r"((b)[0]), "r"((b)[1]))

__device__ __forceinline__ int ld_acquire(const int* p) {
    int v;
    asm volatile("ld.global.acquire.gpu.b32 %0, [%1];" : "=r"(v) : "l"(p) : "memory");
    return v;
}

__device__ __forceinline__ float scale_from_exponent(const int* e) {
    int iv = *e;
    if (iv > -1000000 && iv < 1000000) return exp2f((float)iv);
    return exp2f(__int_as_float(iv));
}

// ---------------- kernel 0a: zero handshake flags (each replay) ----------------
__global__ void zero_flags_kernel() {
    if (threadIdx.x < ITERS) g_flag[threadIdx.x] = 0;
}

// ---------------- kernel 0b: convert x to fp16 ----------------
__global__ void __launch_bounds__(256) conv_x_kernel(const float* __restrict__ xf)
{
    const size_t base = (size_t)blockIdx.x * 2048 + threadIdx.x;
    #pragma unroll
    for (int i = 0; i < 8; ++i) {
        size_t idx = base + i * 256;
        g_x[idx] = __float2half_rn(xf[idx]);
    }
}

// ---------------- fused kernel: 128 GEMM CTAs + 20 producer CTAs ----------------
__global__ void __launch_bounds__(256, 1) fused_kernel(
    const float4* __restrict__ U4,   // one float4 per W element
    const float* __restrict__ q,
    const int* __restrict__ e,
    const float* __restrict__ bias,
    float* __restrict__ out)
{
    const int bid = blockIdx.x;
    const int tid = threadIdx.x;

    if (bid >= GEMM_CTAS) {
        // ============== producer: dequant W chunk-major, in order ==============
        const int p = bid - GEMM_CTAS;
        const int o_beg = p * ROWS_PER_PROD;
        const int o_end = (o_beg + ROWS_PER_PROD < OUTF) ? o_beg + ROWS_PER_PROD : OUTF;

        const float sc = scale_from_exponent(e) * (1.0f / 7.0f);
        const float t0 = q[0] * sc, t1 = q[1] * sc, t2 = q[2] * sc, t3 = q[3] * sc;

        const int w    = tid >> 5;    // warp: row selector
        const int lane = tid & 31;    // k within chunk: lane, lane+32

        #pragma unroll 1
        for (int c = 0; c < ITERS; ++c) {
            const int k0 = c * KC;
            // two rows per iteration for MLP (4 independent LDG.128 in flight)
            #pragma unroll 1
            for (int o = o_beg + w; o < o_end; o += 16) {
                const size_t b0 = (size_t)o * INF + k0 + lane;
                const int o2 = o + 8;
                const size_t b1 = (size_t)o2 * INF + k0 + lane;
                float4 u0 = U4[b0], u1 = U4[b0 + 32];
                float4 u2, u3;
                if (o2 < o_end) { u2 = U4[b1]; u3 = U4[b1 + 32]; }
                g_W[b0]      = __float2half_rn(fmaf(u0.x, t0, fmaf(u0.y, t1, fmaf(u0.z, t2, u0.w * t3))));
                g_W[b0 + 32] = __float2half_rn(fmaf(u1.x, t0, fmaf(u1.y, t1, fmaf(u1.z, t2, u1.w * t3))));
                if (o2 < o_end) {
                    g_W[b1]      = __float2half_rn(fmaf(u2.x, t0, fmaf(u2.y, t1, fmaf(u2.z, t2, u2.w * t3))));
                    g_W[b1 + 32] = __float2half_rn(fmaf(u3.x, t0, fmaf(u3.y, t1, fmaf(u3.z, t2, u3.w * t3))));
                }
            }
            __threadfence();
            __syncthreads();
            if (tid == 0) atomicAdd(&g_flag[c], 1);
        }
        return;
    }

    // ================= consumer: fp16 mma GEMM =================
    extern __shared__ __half smh[];
    const uint32_t sb = smem_u32(smh);
    const int wid  = tid >> 5;
    const int lane = tid & 31;
    const int g    = lane >> 2;
    const int t    = lane & 3;
    const int wrow = wid >> 2;        // 0..1 (M)
    const int wcol = wid & 3;         // 0..3 (N)
    const int n0 = (bid & 31) * TN;
    const int m0 = (bid >> 5) * TM;

    const __half* Ag = g_x + (size_t)m0 * INF;
    const __half* Bg = g_W + (size_t)n0 * INF;

    float acc[4][4][4];
    #pragma unroll
    for (int i = 0; i < 4; ++i)
        #pragma unroll
        for (int j = 0; j < 4; ++j)
            #pragma unroll
            for (int k = 0; k < 4; ++k) acc[i][j][k] = 0.f;

    // single-poller chunk readiness (tid 0 only), with lookahead
    int ready = -1;
    auto ensure_ready = [&](int c) {
        if (c <= ready) return;
        int tgt = c + 8; if (tgt > ITERS - 1) tgt = ITERS - 1;
        if (ld_acquire(&g_flag[tgt]) >= PROD_CTAS) { ready = tgt; return; }
        while (ld_acquire(&g_flag[c]) < PROD_CTAS) __nanosleep(256);
        ready = c;
    };

    auto load_stage = [&](int it, int s) {
        const uint32_t As = sb + (uint32_t)s * STAGE_BYTES;
        const uint32_t Bs = As + TILE_HALVES * 2;
        const int kbase = it * KC;
        #pragma unroll
        for (int i = 0; i < 4; ++i) {
            int cid = i * 256 + tid;
            int r = cid >> 3, c = cid & 7;
            CP_ASYNC16(As + (uint32_t)(r * AS_STRIDE + c * 8) * 2,
                       Ag + (size_t)r * INF + kbase + c * 8);
        }
        #pragma unroll
        for (int i = 0; i < 4; ++i) {
            int cid = i * 256 + tid;
            int r = cid >> 3, c = cid & 7;
            CP_ASYNC16(Bs + (uint32_t)(r * AS_STRIDE + c * 8) * 2,
                       Bg + (size_t)r * INF + kbase + c * 8);
        }
        CP_COMMIT();
    };

    #pragma unroll
    for (int s = 0; s < STAGES - 1; ++s) {
        if (tid == 0) ensure_ready(s);
        __syncthreads();
        load_stage(s, s);
    }

    const uint32_t a_lane_off =
        (uint32_t)((wrow * 64 + (lane & 15)) * AS_STRIDE + ((lane >> 4) << 3)) * 2;
    const uint32_t b_lane_off =
        (uint32_t)((wcol * 32 + ((lane >> 4) << 3) + (lane & 7)) * AS_STRIDE +
                   (((lane >> 3) & 1) << 3)) * 2;

    #pragma unroll 1
    for (int it = 0; it < ITERS; ++it) {
        CP_WAIT(STAGES - 2);
        int nxt = it + STAGES - 1;
        if (tid == 0 && nxt < ITERS) ensure_ready(nxt);
        __syncthreads();
        if (nxt < ITERS) load_stage(nxt, nxt % STAGES);

        const uint32_t As = sb + (uint32_t)(it % STAGES) * STAGE_BYTES;
        const uint32_t Bs = As + TILE_HALVES * 2;

        #pragma unroll
        for (int ks = 0; ks < 4; ++ks) {
            const uint32_t k0b = (uint32_t)(ks * 16) * 2;
            uint32_t a[4][4], b[4][2];
            #pragma unroll
            for (int mt = 0; mt < 4; ++mt) {
                LDSM_X4(a[mt][0], a[mt][1], a[mt][2], a[mt][3],
                        As + a_lane_off + (uint32_t)(mt * 16 * AS_STRIDE) * 2 + k0b);
            }
            #pragma unroll
            for (int np = 0; np < 2; ++np) {
                LDSM_X4(b[2 * np][0], b[2 * np][1], b[2 * np + 1][0], b[2 * np + 1][1],
                        Bs + b_lane_off + (uint32_t)(np * 16 * AS_STRIDE) * 2 + k0b);
            }
            #pragma unroll
            for (int mt = 0; mt < 4; ++mt)
                #pragma unroll
                for (int nt = 0; nt < 4; ++nt)
                    MMA_F16(acc[mt][nt], a[mt], b[nt]);
        }
    }

    // ---- epilogue: registers -> gmem with fused bias, float2 stores ----
    #pragma unroll
    for (int nt = 0; nt < 4; ++nt) {
        const int n = n0 + wcol * 32 + nt * 8 + 2 * t;
        const float b0 = bias[n], b1 = bias[n + 1];
        #pragma unroll
        for (int mt = 0; mt < 4; ++mt) {
            const int m = m0 + wrow * 64 + mt * 16 + g;
            float2 lo = make_float2(acc[mt][nt][0] + b0, acc[mt][nt][1] + b1);
            float2 hi = make_float2(acc[mt][nt][2] + b0, acc[mt][nt][3] + b1);
            *reinterpret_cast<float2*>(out + (size_t)m * OUTF + n) = lo;
            *reinterpret_cast<float2*>(out + (size_t)(m + 8) * OUTF + n) = hi;
        }
    }
}

// ---------------- launch ----------------
extern "C" void kernel_launch(void* const* d_in, const int* in_sizes, int n_in,
                              void* d_out, int out_size)
{
    const float* x = (const float*)d_in[0];   // [512, 4096]
    const float* U = (const float*)d_in[1];   // [4096*4096, 4]
    const float* q = (const float*)d_in[2];   // [4]
    const float* b = (const float*)d_in[3];   // [4096]
    const int*   e = (const int*)d_in[4];     // exponent scalar

    cudaFuncSetAttribute(fused_kernel,
                         cudaFuncAttributeMaxDynamicSharedMemorySize, SMEM_BYTES);

    zero_flags_kernel<<<1, 64>>>();
    conv_x_kernel<<<1024, 256>>>(x);
    fused_kernel<<<GEMM_CTAS + PROD_CTAS, 256, SMEM_BYTES>>>(
        (const float4*)U, q, e, b, (float*)d_out);
}

// round 9
// speedup vs baseline: 2.9434x; 2.9434x over previous
#include <cuda_runtime.h>
#include <cuda_fp16.h>
#include <cstdint>

// Problem constants
#define BATCH 512
#define INF   4096
#define OUTF  4096

// GEMM tiling: CTA 128x128, K-chunk 64 halves (128B rows). Warp grid 2(M) x 4(N).
#define TM 128
#define TN 128
#define KC 64                      // halves per K-chunk
#define ITERS (INF / KC)           // 64
#define STAGES 4
#define LEAD 6                     // produce chunk it+LEAD while consuming it
#define AS_STRIDE 72               // halves per smem row (64 + 8 pad) -> conflict-free LDSM
#define TILE_HALVES (128 * AS_STRIDE)            // 9216 halves = 18432 B
#define STAGE_BYTES (2 * TILE_HALVES * 2)        // A + B = 36864 B
#define SMEM_BYTES (STAGES * STAGE_BYTES)        // 147456 B

#define GEMM_CTAS 128
#define ROWS_PER_CTA 32            // W rows produced per CTA per chunk (128*32 = 4096)

// Scratch + handshake (device globals are the sanctioned scratch mechanism)
__device__ __half g_W[(size_t)OUTF * INF];   // dequantized weight, fp16 (32 MB)
__device__ __half g_x[(size_t)BATCH * INF];  // x, fp16 (4 MB)
__device__ int    g_flag[ITERS];             // per-chunk producer counters (target 128)

// ---------------- PTX helpers (plain-sm_103 legal) ----------------
__device__ __forceinline__ uint32_t smem_u32(const void* p) {
    uint32_t a;
    asm("{ .reg .u64 t; cvta.to.shared.u64 t, %1; cvt.u32.u64 %0, t; }" : "=r"(a) : "l"(p));
    return a;
}

#define CP_ASYNC16(dst_smem, src_gmem) \
    asm volatile("cp.async.cg.shared.global [%0], [%1], 16;" \
                 :: "r"((uint32_t)(dst_smem)), "l"(src_gmem) : "memory")
#define CP_COMMIT() asm volatile("cp.async.commit_group;" ::: "memory")
#define CP_WAIT(n)  asm volatile("cp.async.wait_group %0;" :: "n"(n) : "memory")

#define LDSM_X4(r0, r1, r2, r3, addr) \
    asm volatile("ldmatrix.sync.aligned.m8n8.x4.shared.b16 {%0,%1,%2,%3}, [%4];" \
                 : "=r"(r0), "=r"(r1), "=r"(r2), "=r"(r3) : "r"(addr))

// mma.sync m16n8k16 f16 with f32 accumulate (sm_80 baseline)
#define MMA_F16(d, a, b) \
    asm volatile( \
        "mma.sync.aligned.m16n8k16.row.col.f32.f16.f16.f32 " \
        "{%0,%1,%2,%3}, {%4,%5,%6,%7}, {%8,%9}, {%0,%1,%2,%3};" \
        : "+f"((d)[0]), "+f"((d)[1]), "+f"((d)[2]), "+f"((d)[3]) \
        : "r"((a)[0]), "r"((a)[1]), "r"((a)[2]), "r"((a)[3]), \
          "r"((b)[0]), "r"((b)[1]))

__device__ __forceinline__ int ld_acquire(const int* p) {
    int v;
    asm volatile("ld.global.acquire.gpu.b32 %0, [%1];" : "=r"(v) : "l"(p) : "memory");
    return v;
}

__device__ __forceinline__ float scale_from_exponent(const int* e) {
    int iv = *e;
    if (iv > -1000000 && iv < 1000000) return exp2f((float)iv);
    return exp2f(__int_as_float(iv));
}

// ---------------- kernel 0: convert x to fp16 (+ zero flags in block 0) --------
__global__ void __launch_bounds__(256) conv_x_kernel(const float* __restrict__ xf)
{
    if (blockIdx.x == 0 && threadIdx.x < ITERS) g_flag[threadIdx.x] = 0;
    const size_t base = (size_t)blockIdx.x * 2048 + threadIdx.x;
    #pragma unroll
    for (int i = 0; i < 8; ++i) {
        size_t idx = base + i * 256;
        g_x[idx] = __float2half_rn(xf[idx]);
    }
}

// ---------------- fused kernel: 128 CTAs, each GEMM consumer + W producer ------
__global__ void __launch_bounds__(256, 1) fused_kernel(
    const float4* __restrict__ U4,   // one float4 per W element
    const float* __restrict__ q,
    const int* __restrict__ e,
    const float* __restrict__ bias,
    float* __restrict__ out)
{
    extern __shared__ __half smh[];
    const uint32_t sb = smem_u32(smh);
    const int bid  = blockIdx.x;
    const int tid  = threadIdx.x;
    const int wid  = tid >> 5;
    const int lane = tid & 31;
    const int g    = lane >> 2;
    const int t    = lane & 3;
    const int wrow = wid >> 2;        // 0..1 (M)
    const int wcol = wid & 3;         // 0..3 (N)
    const int n0 = (bid & 31) * TN;
    const int m0 = (bid >> 5) * TM;

    // ---- producer constants ----
    const float sc = scale_from_exponent(e) * (1.0f / 7.0f);
    const float t0 = q[0] * sc, t1 = q[1] * sc, t2 = q[2] * sc, t3 = q[3] * sc;
    const int prow_base = bid * ROWS_PER_CTA;   // this CTA's 32 W rows per chunk

    // per-thread produce mapping: element idx = i*256+tid over 32x64 slice
    // row = prow_base + idx/64, k = chunk*64 + idx%64 (lanes adjacent -> coalesced)
    auto produce_load = [&](int chunk, float4* u) {
        const size_t kbase = (size_t)chunk * KC;
        #pragma unroll
        for (int i = 0; i < 8; ++i) {
            int idx = i * 256 + tid;
            size_t gi = (size_t)(prow_base + (idx >> 6)) * INF + kbase + (idx & 63);
            u[i] = U4[gi];
        }
    };
    auto produce_store = [&](int chunk, const float4* u) {
        const size_t kbase = (size_t)chunk * KC;
        #pragma unroll
        for (int i = 0; i < 8; ++i) {
            int idx = i * 256 + tid;
            size_t gi = (size_t)(prow_base + (idx >> 6)) * INF + kbase + (idx & 63);
            g_W[gi] = __float2half_rn(
                fmaf(u[i].x, t0, fmaf(u[i].y, t1, fmaf(u[i].z, t2, u[i].w * t3))));
        }
    };

    // ---- prologue: produce chunks 0..LEAD-1 ----
    #pragma unroll 1
    for (int c = 0; c < LEAD; ++c) {
        float4 u[8];
        produce_load(c, u);
        produce_store(c, u);
    }
    __threadfence();
    __syncthreads();
    if (tid == 0) {
        #pragma unroll
        for (int c = 0; c < LEAD; ++c) atomicAdd(&g_flag[c], 1);
    }

    // ---- consumer setup ----
    const __half* Ag = g_x + (size_t)m0 * INF;
    const __half* Bg = g_W + (size_t)n0 * INF;

    float acc[4][4][4];
    #pragma unroll
    for (int i = 0; i < 4; ++i)
        #pragma unroll
        for (int j = 0; j < 4; ++j)
            #pragma unroll
            for (int k = 0; k < 4; ++k) acc[i][j][k] = 0.f;

    int ready = -1;   // tid 0 only
    auto ensure_ready = [&](int c) {
        if (c <= ready) return;
        int tgt = c + 8; if (tgt > ITERS - 1) tgt = ITERS - 1;
        if (ld_acquire(&g_flag[tgt]) >= GEMM_CTAS) { ready = tgt; return; }
        while (ld_acquire(&g_flag[c]) < GEMM_CTAS) __nanosleep(128);
        ready = c;
    };

    auto load_stage = [&](int it, int s) {
        const uint32_t As = sb + (uint32_t)s * STAGE_BYTES;
        const uint32_t Bs = As + TILE_HALVES * 2;
        const int kbase = it * KC;
        #pragma unroll
        for (int i = 0; i < 4; ++i) {
            int cid = i * 256 + tid;
            int r = cid >> 3, c = cid & 7;
            CP_ASYNC16(As + (uint32_t)(r * AS_STRIDE + c * 8) * 2,
                       Ag + (size_t)r * INF + kbase + c * 8);
        }
        #pragma unroll
        for (int i = 0; i < 4; ++i) {
            int cid = i * 256 + tid;
            int r = cid >> 3, c = cid & 7;
            CP_ASYNC16(Bs + (uint32_t)(r * AS_STRIDE + c * 8) * 2,
                       Bg + (size_t)r * INF + kbase + c * 8);
        }
        CP_COMMIT();
    };

    #pragma unroll
    for (int s = 0; s < STAGES - 1; ++s) {
        if (tid == 0) ensure_ready(s);
        __syncthreads();
        load_stage(s, s);
    }

    const uint32_t a_lane_off =
        (uint32_t)((wrow * 64 + (lane & 15)) * AS_STRIDE + ((lane >> 4) << 3)) * 2;
    const uint32_t b_lane_off =
        (uint32_t)((wcol * 32 + ((lane >> 4) << 3) + (lane & 7)) * AS_STRIDE +
                   (((lane >> 3) & 1) << 3)) * 2;

    #pragma unroll 1
    for (int it = 0; it < ITERS; ++it) {
        CP_WAIT(STAGES - 2);
        const int nxt = it + STAGES - 1;
        if (tid == 0 && nxt < ITERS) ensure_ready(nxt);
        __syncthreads();
        if (nxt < ITERS) load_stage(nxt, nxt % STAGES);

        // issue producer loads for chunk it+LEAD (latency hidden under MMAs)
        const int pch = it + LEAD;
        float4 u[8];
        if (pch < ITERS) produce_load(pch, u);

        const uint32_t As = sb + (uint32_t)(it % STAGES) * STAGE_BYTES;
        const uint32_t Bs = As + TILE_HALVES * 2;

        #pragma unroll
        for (int ks = 0; ks < 4; ++ks) {
            const uint32_t k0b = (uint32_t)(ks * 16) * 2;
            uint32_t a[4][4], b[4][2];
            #pragma unroll
            for (int mt = 0; mt < 4; ++mt) {
                LDSM_X4(a[mt][0], a[mt][1], a[mt][2], a[mt][3],
                        As + a_lane_off + (uint32_t)(mt * 16 * AS_STRIDE) * 2 + k0b);
            }
            #pragma unroll
            for (int np = 0; np < 2; ++np) {
                LDSM_X4(b[2 * np][0], b[2 * np][1], b[2 * np + 1][0], b[2 * np + 1][1],
                        Bs + b_lane_off + (uint32_t)(np * 16 * AS_STRIDE) * 2 + k0b);
            }
            #pragma unroll
            for (int mt = 0; mt < 4; ++mt)
                #pragma unroll
                for (int nt = 0; nt < 4; ++nt)
                    MMA_F16(acc[mt][nt], a[mt], b[nt]);
        }

        if (pch < ITERS) {
            produce_store(pch, u);
            __threadfence();
            __syncthreads();
            if (tid == 0) atomicAdd(&g_flag[pch], 1);
        }
    }

    // ---- epilogue: registers -> gmem with fused bias, float2 stores ----
    #pragma unroll
    for (int nt = 0; nt < 4; ++nt) {
        const int n = n0 + wcol * 32 + nt * 8 + 2 * t;
        const float b0 = bias[n], b1 = bias[n + 1];
        #pragma unroll
        for (int mt = 0; mt < 4; ++mt) {
            const int m = m0 + wrow * 64 + mt * 16 + g;
            float2 lo = make_float2(acc[mt][nt][0] + b0, acc[mt][nt][1] + b1);
            float2 hi = make_float2(acc[mt][nt][2] + b0, acc[mt][nt][3] + b1);
            *reinterpret_cast<float2*>(out + (size_t)m * OUTF + n) = lo;
            *reinterpret_cast<float2*>(out + (size_t)(m + 8) * OUTF + n) = hi;
        }
    }
}

// ---------------- launch ----------------
extern "C" void kernel_launch(void* const* d_in, const int* in_sizes, int n_in,
                              void* d_out, int out_size)
{
    const float* x = (const float*)d_in[0];   // [512, 4096]
    const float* U = (const float*)d_in[1];   // [4096*4096, 4]
    const float* q = (const float*)d_in[2];   // [4]
    const float* b = (const float*)d_in[3];   // [4096]
    const int*   e = (const int*)d_in[4];     // exponent scalar

    cudaFuncSetAttribute(fused_kernel,
                         cudaFuncAttributeMaxDynamicSharedMemorySize, SMEM_BYTES);

    conv_x_kernel<<<1024, 256>>>(x);          // also zeroes flags (block 0)
    fused_kernel<<<GEMM_CTAS, 256, SMEM_BYTES>>>(
        (const float4*)U, q, e, b, (float*)d_out);
}

// round 10
// speedup vs baseline: 3.5210x; 1.1962x over previous
#include <cuda_runtime.h>
#include <cuda_fp16.h>
#include <cstdint>

// Problem constants
#define BATCH 512
#define INF   4096
#define OUTF  4096

// GEMM tiling: CTA 128x128, K-chunk 64 halves (128B rows). Warp grid 2(M) x 4(N).
#define TM 128
#define TN 128
#define KC 64                      // halves per K-chunk
#define ITERS (INF / KC)           // 64
#define STAGES 4
#define AS_STRIDE 72               // halves per smem row (64 + 8 pad) -> conflict-free LDSM
#define TILE_HALVES (128 * AS_STRIDE)            // 9216 halves = 18432 B
#define STAGE_BYTES (2 * TILE_HALVES * 2)        // A + B = 36864 B
#define SMEM_BYTES (STAGES * STAGE_BYTES)        // 147456 B

#define GEMM_CTAS 128
#define NTHREADS 320               // warps 0-7 consumers, warps 8-9 free-running producers

// Scratch + handshake (device globals are the sanctioned scratch mechanism)
__device__ __half g_W[(size_t)OUTF * INF];   // dequantized weight, fp16 (32 MB; fits L2)
__device__ __half g_x[(size_t)BATCH * INF];  // x, fp16 (4 MB)
__device__ int    g_flag[ITERS];             // per-chunk producer counters (target 128)

// ---------------- PTX helpers (plain-sm_103 legal) ----------------
__device__ __forceinline__ uint32_t smem_u32(const void* p) {
    uint32_t a;
    asm("{ .reg .u64 t; cvta.to.shared.u64 t, %1; cvt.u32.u64 %0, t; }" : "=r"(a) : "l"(p));
    return a;
}

#define CP_ASYNC16(dst_smem, src_gmem) \
    asm volatile("cp.async.cg.shared.global [%0], [%1], 16;" \
                 :: "r"((uint32_t)(dst_smem)), "l"(src_gmem) : "memory")
#define CP_COMMIT() asm volatile("cp.async.commit_group;" ::: "memory")
#define CP_WAIT(n)  asm volatile("cp.async.wait_group %0;" :: "n"(n) : "memory")

// named barriers (avoid bar 0: producer warps never join consumer syncs)
#define BAR_PROD() asm volatile("bar.sync 1, 64;"  ::: "memory")
#define BAR_CONS() asm volatile("bar.sync 2, 256;" ::: "memory")

#define LDSM_X4(r0, r1, r2, r3, addr) \
    asm volatile("ldmatrix.sync.aligned.m8n8.x4.shared.b16 {%0,%1,%2,%3}, [%4];" \
                 : "=r"(r0), "=r"(r1), "=r"(r2), "=r"(r3) : "r"(addr))

// mma.sync m16n8k16 f16 with f32 accumulate (sm_80 baseline)
#define MMA_F16(d, a, b) \
    asm volatile( \
        "mma.sync.aligned.m16n8k16.row.col.f32.f16.f16.f32 " \
        "{%0,%1,%2,%3}, {%4,%5,%6,%7}, {%8,%9}, {%0,%1,%2,%3};" \
        : "+f"((d)[0]), "+f"((d)[1]), "+f"((d)[2]), "+f"((d)[3]) \
        : "r"((a)[0]), "r"((a)[1]), "r"((a)[2]), "r"((a)[3]), \
          "r"((b)[0]), "r"((b)[1]))

__device__ __forceinline__ int ld_acquire(const int* p) {
    int v;
    asm volatile("ld.global.acquire.gpu.b32 %0, [%1];" : "=r"(v) : "l"(p) : "memory");
    return v;
}

__device__ __forceinline__ float scale_from_exponent(const int* e) {
    int iv = *e;
    if (iv > -1000000 && iv < 1000000) return exp2f((float)iv);
    return exp2f(__int_as_float(iv));
}

// ---------------- kernel 0: convert x to fp16 + zero flags ----------------
__global__ void __launch_bounds__(256) conv_x_kernel(const float* __restrict__ xf)
{
    if (blockIdx.x == 0 && threadIdx.x < ITERS) g_flag[threadIdx.x] = 0;
    const size_t base = (size_t)blockIdx.x * 2048 + threadIdx.x;
    #pragma unroll
    for (int i = 0; i < 8; ++i) {
        size_t idx = base + i * 256;
        g_x[idx] = __float2half_rn(xf[idx]);
    }
}

// ---------------- fused kernel: 128 CTAs, consumer warps + producer warps ------
__global__ void __launch_bounds__(NTHREADS, 1) fused_kernel(
    const float4* __restrict__ U4,   // one float4 per W element
    const float* __restrict__ q,
    const int* __restrict__ e,
    const float* __restrict__ bias,
    float* __restrict__ out)
{
    const int bid = blockIdx.x;
    const int tid = threadIdx.x;

    if (tid >= 256) {
        // ========= producers (2 warps): stream this CTA's 32 W rows, all chunks =========
        const float sc = scale_from_exponent(e) * (1.0f / 7.0f);
        const float t0 = q[0] * sc, t1 = q[1] * sc, t2 = q[2] * sc, t3 = q[3] * sc;
        const int ptid = tid - 256;            // 0..63 = column within chunk
        const int prow = bid * 32;             // this CTA's W row slice

        #pragma unroll 1
        for (int c = 0; c < ITERS; ++c) {
            const size_t cb = (size_t)c * KC + ptid;
            #pragma unroll
            for (int h = 0; h < 2; ++h) {
                float4 u[16];
                #pragma unroll
                for (int j = 0; j < 16; ++j)       // 16 LDG.128 in flight per lane
                    u[j] = U4[(size_t)(prow + h * 16 + j) * INF + cb];
                #pragma unroll
                for (int j = 0; j < 16; ++j)
                    g_W[(size_t)(prow + h * 16 + j) * INF + cb] = __float2half_rn(
                        fmaf(u[j].x, t0, fmaf(u[j].y, t1, fmaf(u[j].z, t2, u[j].w * t3))));
            }
            __threadfence();
            BAR_PROD();
            if (ptid == 0) atomicAdd(&g_flag[c], 1);
        }
        return;
    }

    // ================= consumers (8 warps): fp16 mma GEMM =================
    extern __shared__ __half smh[];
    const uint32_t sb = smem_u32(smh);
    const int wid  = tid >> 5;
    const int lane = tid & 31;
    const int g    = lane >> 2;
    const int t    = lane & 3;
    const int wrow = wid >> 2;        // 0..1 (M)
    const int wcol = wid & 3;         // 0..3 (N)
    const int n0 = (bid & 31) * TN;
    const int m0 = (bid >> 5) * TM;

    const __half* Ag = g_x + (size_t)m0 * INF;
    const __half* Bg = g_W + (size_t)n0 * INF;

    float acc[4][4][4];
    #pragma unroll
    for (int i = 0; i < 4; ++i)
        #pragma unroll
        for (int j = 0; j < 4; ++j)
            #pragma unroll
            for (int k = 0; k < 4; ++k) acc[i][j][k] = 0.f;

    // single-poller chunk readiness (tid 0 only), with lookahead
    int ready = -1;
    auto ensure_ready = [&](int c) {
        if (c <= ready) return;
        int tgt = c + 8; if (tgt > ITERS - 1) tgt = ITERS - 1;
        if (ld_acquire(&g_flag[tgt]) >= GEMM_CTAS) { ready = tgt; return; }
        while (ld_acquire(&g_flag[c]) < GEMM_CTAS) __nanosleep(128);
        ready = c;
    };

    auto load_stage = [&](int it, int s) {
        const uint32_t As = sb + (uint32_t)s * STAGE_BYTES;
        const uint32_t Bs = As + TILE_HALVES * 2;
        const int kbase = it * KC;
        #pragma unroll
        for (int i = 0; i < 4; ++i) {
            int cid = i * 256 + tid;
            int r = cid >> 3, c = cid & 7;
            CP_ASYNC16(As + (uint32_t)(r * AS_STRIDE + c * 8) * 2,
                       Ag + (size_t)r * INF + kbase + c * 8);
        }
        #pragma unroll
        for (int i = 0; i < 4; ++i) {
            int cid = i * 256 + tid;
            int r = cid >> 3, c = cid & 7;
            CP_ASYNC16(Bs + (uint32_t)(r * AS_STRIDE + c * 8) * 2,
                       Bg + (size_t)r * INF + kbase + c * 8);
        }
        CP_COMMIT();
    };

    #pragma unroll
    for (int s = 0; s < STAGES - 1; ++s) {
        if (tid == 0) ensure_ready(s);
        BAR_CONS();
        load_stage(s, s);
    }

    const uint32_t a_lane_off =
        (uint32_t)((wrow * 64 + (lane & 15)) * AS_STRIDE + ((lane >> 4) << 3)) * 2;
    const uint32_t b_lane_off =
        (uint32_t)((wcol * 32 + ((lane >> 4) << 3) + (lane & 7)) * AS_STRIDE +
                   (((lane >> 3) & 1) << 3)) * 2;

    #pragma unroll 1
    for (int it = 0; it < ITERS; ++it) {
        CP_WAIT(STAGES - 2);
        const int nxt = it + STAGES - 1;
        if (tid == 0 && nxt < ITERS) ensure_ready(nxt);
        BAR_CONS();
        if (nxt < ITERS) load_stage(nxt, nxt % STAGES);

        const uint32_t As = sb + (uint32_t)(it % STAGES) * STAGE_BYTES;
        const uint32_t Bs = As + TILE_HALVES * 2;

        #pragma unroll
        for (int ks = 0; ks < 4; ++ks) {
            const uint32_t k0b = (uint32_t)(ks * 16) * 2;
            uint32_t a[4][4], b[4][2];
            #pragma unroll
            for (int mt = 0; mt < 4; ++mt) {
                LDSM_X4(a[mt][0], a[mt][1], a[mt][2], a[mt][3],
                        As + a_lane_off + (uint32_t)(mt * 16 * AS_STRIDE) * 2 + k0b);
            }
            #pragma unroll
            for (int np = 0; np < 2; ++np) {
                LDSM_X4(b[2 * np][0], b[2 * np][1], b[2 * np + 1][0], b[2 * np + 1][1],
                        Bs + b_lane_off + (uint32_t)(np * 16 * AS_STRIDE) * 2 + k0b);
            }
            #pragma unroll
            for (int mt = 0; mt < 4; ++mt)
                #pragma unroll
                for (int nt = 0; nt < 4; ++nt)
                    MMA_F16(acc[mt][nt], a[mt], b[nt]);
        }
    }

    // ---- epilogue: registers -> gmem with fused bias, float2 stores ----
    #pragma unroll
    for (int nt = 0; nt < 4; ++nt) {
        const int n = n0 + wcol * 32 + nt * 8 + 2 * t;
        const float b0 = bias[n], b1 = bias[n + 1];
        #pragma unroll
        for (int mt = 0; mt < 4; ++mt) {
            const int m = m0 + wrow * 64 + mt * 16 + g;
            float2 lo = make_float2(acc[mt][nt][0] + b0, acc[mt][nt][1] + b1);
            float2 hi = make_float2(acc[mt][nt][2] + b0, acc[mt][nt][3] + b1);
            *reinterpret_cast<float2*>(out + (size_t)m * OUTF + n) = lo;
            *reinterpret_cast<float2*>(out + (size_t)(m + 8) * OUTF + n) = hi;
        }
    }
}

// ---------------- launch ----------------
extern "C" void kernel_launch(void* const* d_in, const int* in_sizes, int n_in,
                              void* d_out, int out_size)
{
    const float* x = (const float*)d_in[0];   // [512, 4096]
    const float* U = (const float*)d_in[1];   // [4096*4096, 4]
    const float* q = (const float*)d_in[2];   // [4]
    const float* b = (const float*)d_in[3];   // [4096]
    const int*   e = (const int*)d_in[4];     // exponent scalar

    cudaFuncSetAttribute(fused_kernel,
                         cudaFuncAttributeMaxDynamicSharedMemorySize, SMEM_BYTES);

    conv_x_kernel<<<1024, 256>>>(x);          // also zeroes flags (block 0)
    fused_kernel<<<GEMM_CTAS, NTHREADS, SMEM_BYTES>>>(
        (const float4*)U, q, e, b, (float*)d_out);
}

// round 11
// speedup vs baseline: 3.8287x; 1.0874x over previous
#include <cuda_runtime.h>
#include <cuda_fp16.h>
#include <cstdint>

// Problem constants
#define BATCH 512
#define INF   4096
#define OUTF  4096

// GEMM tiling: CTA 128x128, K-chunk 64 halves (128B rows). Warp grid 2(M) x 4(N).
#define TM 128
#define TN 128
#define KC 64                      // halves per K-chunk
#define ITERS (INF / KC)           // 64
#define STAGES 4
#define AS_STRIDE 72               // halves per smem row (64 + 8 pad) -> conflict-free LDSM
#define TILE_HALVES (128 * AS_STRIDE)            // 9216 halves = 18432 B
#define STAGE_BYTES (2 * TILE_HALVES * 2)        // A + B = 36864 B
#define SMEM_BYTES (STAGES * STAGE_BYTES)        // 147456 B

#define GEMM_CTAS 128
#define NTHREADS 384               // warps 0-7 consumers, warps 8-11 producers
#define NGROUPS 32                 // n-tiles; flag granularity
#define FLAG_TARGET 512            // 4 producer CTAs x 128 threads per group

// Scratch + handshake (device globals are the sanctioned scratch mechanism)
__device__ __half g_W[(size_t)OUTF * INF];   // dequantized weight, fp16 (32 MB)
__device__ __half g_x[(size_t)BATCH * INF];  // x, fp16 (4 MB)
__device__ int    g_flag[NGROUPS * ITERS];   // per (n-tile, chunk) release counters

// ---------------- PTX helpers (plain-sm_103 legal) ----------------
__device__ __forceinline__ uint32_t smem_u32(const void* p) {
    uint32_t a;
    asm("{ .reg .u64 t; cvta.to.shared.u64 t, %1; cvt.u32.u64 %0, t; }" : "=r"(a) : "l"(p));
    return a;
}

#define CP_ASYNC16(dst_smem, src_gmem) \
    asm volatile("cp.async.cg.shared.global [%0], [%1], 16;" \
                 :: "r"((uint32_t)(dst_smem)), "l"(src_gmem) : "memory")
#define CP_COMMIT() asm volatile("cp.async.commit_group;" ::: "memory")
#define CP_WAIT(n)  asm volatile("cp.async.wait_group %0;" :: "n"(n) : "memory")

// consumer-only named barrier (producer warps never participate)
#define BAR_CONS() asm volatile("bar.sync 2, 256;" ::: "memory")

#define LDSM_X4(r0, r1, r2, r3, addr) \
    asm volatile("ldmatrix.sync.aligned.m8n8.x4.shared.b16 {%0,%1,%2,%3}, [%4];" \
                 : "=r"(r0), "=r"(r1), "=r"(r2), "=r"(r3) : "r"(addr))

// mma.sync m16n8k16 f16 with f32 accumulate (sm_80 baseline)
#define MMA_F16(d, a, b) \
    asm volatile( \
        "mma.sync.aligned.m16n8k16.row.col.f32.f16.f16.f32 " \
        "{%0,%1,%2,%3}, {%4,%5,%6,%7}, {%8,%9}, {%0,%1,%2,%3};" \
        : "+f"((d)[0]), "+f"((d)[1]), "+f"((d)[2]), "+f"((d)[3]) \
        : "r"((a)[0]), "r"((a)[1]), "r"((a)[2]), "r"((a)[3]), \
          "r"((b)[0]), "r"((b)[1]))

__device__ __forceinline__ int ld_acquire(const int* p) {
    int v;
    asm volatile("ld.global.acquire.gpu.b32 %0, [%1];" : "=r"(v) : "l"(p) : "memory");
    return v;
}
// per-thread release publish: orders THIS thread's prior global stores
#define RED_RELEASE_ADD1(addr) \
    asm volatile("red.release.gpu.global.add.s32 [%0], 1;" :: "l"(addr) : "memory")

__device__ __forceinline__ float scale_from_exponent(const int* e) {
    int iv = *e;
    if (iv > -1000000 && iv < 1000000) return exp2f((float)iv);
    return exp2f(__int_as_float(iv));
}

// ---------------- kernel 0: convert x to fp16 + zero flags ----------------
__global__ void __launch_bounds__(256) conv_x_kernel(const float* __restrict__ xf)
{
    if (blockIdx.x == 0) {
        #pragma unroll
        for (int i = 0; i < NGROUPS * ITERS / 256; ++i)
            g_flag[i * 256 + threadIdx.x] = 0;
    }
    const size_t base = (size_t)blockIdx.x * 2048 + threadIdx.x;
    #pragma unroll
    for (int i = 0; i < 8; ++i) {
        size_t idx = base + i * 256;
        g_x[idx] = __float2half_rn(xf[idx]);
    }
}

// ---------------- fused kernel: 128 CTAs, 8 consumer + 4 producer warps --------
__global__ void __launch_bounds__(NTHREADS, 1) fused_kernel(
    const float4* __restrict__ U4,   // one float4 per W element
    const float* __restrict__ q,
    const int* __restrict__ e,
    const float* __restrict__ bias,
    float* __restrict__ out)
{
    const int bid = blockIdx.x;
    const int tid = threadIdx.x;

    if (tid >= 256) {
        // ===== producers (4 warps): this CTA's 32 W rows, pipelined, lock-free =====
        const float sc = scale_from_exponent(e) * (1.0f / 7.0f);
        const float t0 = q[0] * sc, t1 = q[1] * sc, t2 = q[2] * sc, t3 = q[3] * sc;
        const int pw  = tid - 256;           // 0..127
        const int hi  = pw >> 6;             // 0..1
        const int col = pw & 63;             // column within chunk
        const int prow = bid * 32;           // this CTA's W row slice
        int* const flag = g_flag + (bid >> 2) * ITERS;   // group = n-tile bid/4

        // batch b (0/1): rows 2*(b*8+i)+hi, i=0..7 (16 elems/thread/chunk total)
        auto issue8 = [&](int c, int b, float4* u) {
            #pragma unroll
            for (int i = 0; i < 8; ++i) {
                int row = 2 * (b * 8 + i) + hi;
                u[i] = U4[(size_t)(prow + row) * INF + (size_t)c * KC + col];
            }
        };
        auto process8 = [&](int c, int b, const float4* u) {
            #pragma unroll
            for (int i = 0; i < 8; ++i) {
                int row = 2 * (b * 8 + i) + hi;
                g_W[(size_t)(prow + row) * INF + (size_t)c * KC + col] = __float2half_rn(
                    fmaf(u[i].x, t0, fmaf(u[i].y, t1, fmaf(u[i].z, t2, u[i].w * t3))));
            }
        };

        float4 ua[8], ub[8];
        issue8(0, 0, ua);
        #pragma unroll 1
        for (int c = 0; c < ITERS; ++c) {
            issue8(c, 1, ub);                     // overlap with ua processing
            process8(c, 0, ua);
            if (c + 1 < ITERS) issue8(c + 1, 0, ua);   // cross-chunk pipeline
            process8(c, 1, ub);
            RED_RELEASE_ADD1(flag + c);           // per-thread release publish
        }
        return;
    }

    // ================= consumers (8 warps): fp16 mma GEMM =================
    extern __shared__ __half smh[];
    const uint32_t sb = smem_u32(smh);
    const int wid  = tid >> 5;
    const int lane = tid & 31;
    const int g    = lane >> 2;
    const int t    = lane & 3;
    const int wrow = wid >> 2;        // 0..1 (M)
    const int wcol = wid & 3;         // 0..3 (N)
    const int n0 = (bid & 31) * TN;
    const int m0 = (bid >> 5) * TM;

    const __half* Ag = g_x + (size_t)m0 * INF;
    const __half* Bg = g_W + (size_t)n0 * INF;
    const int* const flag = g_flag + (bid & 31) * ITERS;   // this n-tile's flags

    float acc[4][4][4];
    #pragma unroll
    for (int i = 0; i < 4; ++i)
        #pragma unroll
        for (int j = 0; j < 4; ++j)
            #pragma unroll
            for (int k = 0; k < 4; ++k) acc[i][j][k] = 0.f;

    // single-poller chunk readiness (tid 0 only), with lookahead
    int ready = -1;
    auto ensure_ready = [&](int c) {
        if (c <= ready) return;
        int tgt = c + 8; if (tgt > ITERS - 1) tgt = ITERS - 1;
        if (ld_acquire(flag + tgt) >= FLAG_TARGET) { ready = tgt; return; }
        while (ld_acquire(flag + c) < FLAG_TARGET) __nanosleep(128);
        ready = c;
    };

    auto load_stage = [&](int it, int s) {
        const uint32_t As = sb + (uint32_t)s * STAGE_BYTES;
        const uint32_t Bs = As + TILE_HALVES * 2;
        const int kbase = it * KC;
        #pragma unroll
        for (int i = 0; i < 4; ++i) {
            int cid = i * 256 + tid;
            int r = cid >> 3, c = cid & 7;
            CP_ASYNC16(As + (uint32_t)(r * AS_STRIDE + c * 8) * 2,
                       Ag + (size_t)r * INF + kbase + c * 8);
        }
        #pragma unroll
        for (int i = 0; i < 4; ++i) {
            int cid = i * 256 + tid;
            int r = cid >> 3, c = cid & 7;
            CP_ASYNC16(Bs + (uint32_t)(r * AS_STRIDE + c * 8) * 2,
                       Bg + (size_t)r * INF + kbase + c * 8);
        }
        CP_COMMIT();
    };

    #pragma unroll
    for (int s = 0; s < STAGES - 1; ++s) {
        if (tid == 0) ensure_ready(s);
        BAR_CONS();
        load_stage(s, s);
    }

    const uint32_t a_lane_off =
        (uint32_t)((wrow * 64 + (lane & 15)) * AS_STRIDE + ((lane >> 4) << 3)) * 2;
    const uint32_t b_lane_off =
        (uint32_t)((wcol * 32 + ((lane >> 4) << 3) + (lane & 7)) * AS_STRIDE +
                   (((lane >> 3) & 1) << 3)) * 2;

    #pragma unroll 1
    for (int it = 0; it < ITERS; ++it) {
        CP_WAIT(STAGES - 2);
        const int nxt = it + STAGES - 1;
        if (tid == 0 && nxt < ITERS) ensure_ready(nxt);
        BAR_CONS();
        if (nxt < ITERS) load_stage(nxt, nxt % STAGES);

        const uint32_t As = sb + (uint32_t)(it % STAGES) * STAGE_BYTES;
        const uint32_t Bs = As + TILE_HALVES * 2;

        #pragma unroll
        for (int ks = 0; ks < 4; ++ks) {
            const uint32_t k0b = (uint32_t)(ks * 16) * 2;
            uint32_t a[4][4], b[4][2];
            #pragma unroll
            for (int mt = 0; mt < 4; ++mt) {
                LDSM_X4(a[mt][0], a[mt][1], a[mt][2], a[mt][3],
                        As + a_lane_off + (uint32_t)(mt * 16 * AS_STRIDE) * 2 + k0b);
            }
            #pragma unroll
            for (int np = 0; np < 2; ++np) {
                LDSM_X4(b[2 * np][0], b[2 * np][1], b[2 * np + 1][0], b[2 * np + 1][1],
                        Bs + b_lane_off + (uint32_t)(np * 16 * AS_STRIDE) * 2 + k0b);
            }
            #pragma unroll
            for (int mt = 0; mt < 4; ++mt)
                #pragma unroll
                for (int nt = 0; nt < 4; ++nt)
                    MMA_F16(acc[mt][nt], a[mt], b[nt]);
        }
    }

    // ---- epilogue: registers -> gmem with fused bias, float2 stores ----
    #pragma unroll
    for (int nt = 0; nt < 4; ++nt) {
        const int n = n0 + wcol * 32 + nt * 8 + 2 * t;
        const float b0 = bias[n], b1 = bias[n + 1];
        #pragma unroll
        for (int mt = 0; mt < 4; ++mt) {
            const int m = m0 + wrow * 64 + mt * 16 + g;
            float2 lo = make_float2(acc[mt][nt][0] + b0, acc[mt][nt][1] + b1);
            float2 hi = make_float2(acc[mt][nt][2] + b0, acc[mt][nt][3] + b1);
            *reinterpret_cast<float2*>(out + (size_t)m * OUTF + n) = lo;
            *reinterpret_cast<float2*>(out + (size_t)(m + 8) * OUTF + n) = hi;
        }
    }
}

// ---------------- launch ----------------
extern "C" void kernel_launch(void* const* d_in, const int* in_sizes, int n_in,
                              void* d_out, int out_size)
{
    const float* x = (const float*)d_in[0];   // [512, 4096]
    const float* U = (const float*)d_in[1];   // [4096*4096, 4]
    const float* q = (const float*)d_in[2];   // [4]
    const float* b = (const float*)d_in[3];   // [4096]
    const int*   e = (const int*)d_in[4];     // exponent scalar

    cudaFuncSetAttribute(fused_kernel,
                         cudaFuncAttributeMaxDynamicSharedMemorySize, SMEM_BYTES);

    conv_x_kernel<<<1024, 256>>>(x);          // also zeroes flags (block 0)
    fused_kernel<<<GEMM_CTAS, NTHREADS, SMEM_BYTES>>>(
        (const float4*)U, q, e, b, (float*)d_out);
}

// round 12
// speedup vs baseline: 7.0090x; 1.8306x over previous
#include <cuda_runtime.h>
#include <cuda_fp16.h>
#include <cstdint>

// Problem constants
#define BATCH 512
#define INF   4096
#define OUTF  4096

// Fused-dequant GEMM: CTA = 32 out-rows x 512 batch, K-chunk 64 W-elements.
#define KC 64
#define ITERS (INF / KC)          // 64
#define TN 32
#define NCTAS (OUTF / TN)         // 128

// smem layout (bytes): A stages are 512 rows x 128B (SW128 XOR swizzle),
// U stages are 32x64 float4 linear, B is single 32x128B (SW128 XOR).
#define OFF_A0 0
#define OFF_A1 65536
#define OFF_U0 131072
#define OFF_U1 163840
#define OFF_B  196608
#define SMEM_BYTES 200704

// Scratch (device global = sanctioned scratch)
__device__ __half g_x[(size_t)BATCH * INF];  // x in fp16 (4 MB)

// ---------------- PTX helpers (plain-sm_103 legal) ----------------
__device__ __forceinline__ uint32_t smem_u32(const void* p) {
    uint32_t a;
    asm("{ .reg .u64 t; cvta.to.shared.u64 t, %1; cvt.u32.u64 %0, t; }" : "=r"(a) : "l"(p));
    return a;
}

#define CP_ASYNC16(dst_smem, src_gmem) \
    asm volatile("cp.async.cg.shared.global [%0], [%1], 16;" \
                 :: "r"((uint32_t)(dst_smem)), "l"(src_gmem) : "memory")
#define CP_COMMIT() asm volatile("cp.async.commit_group;" ::: "memory")
#define CP_WAIT(n)  asm volatile("cp.async.wait_group %0;" :: "n"(n) : "memory")

#define LDSM_X4(r0, r1, r2, r3, addr) \
    asm volatile("ldmatrix.sync.aligned.m8n8.x4.shared.b16 {%0,%1,%2,%3}, [%4];" \
                 : "=r"(r0), "=r"(r1), "=r"(r2), "=r"(r3) : "r"(addr))

#define MMA_F16(d, a, b) \
    asm volatile( \
        "mma.sync.aligned.m16n8k16.row.col.f32.f16.f16.f32 " \
        "{%0,%1,%2,%3}, {%4,%5,%6,%7}, {%8,%9}, {%0,%1,%2,%3};" \
        : "+f"((d)[0]), "+f"((d)[1]), "+f"((d)[2]), "+f"((d)[3]) \
        : "r"((a)[0]), "r"((a)[1]), "r"((a)[2]), "r"((a)[3]), \
          "r"((b)[0]), "r"((b)[1]))

#define LDS_F32X4(v, addr) \
    asm volatile("ld.shared.v4.f32 {%0,%1,%2,%3}, [%4];" \
                 : "=f"((v).x), "=f"((v).y), "=f"((v).z), "=f"((v).w) : "r"(addr))
#define STS_B16(addr, h) \
    asm volatile("st.shared.b16 [%0], %1;" :: "r"(addr), "h"(h) : "memory")

__device__ __forceinline__ float scale_from_exponent(const int* e) {
    int iv = *e;
    if (iv > -1000000 && iv < 1000000) return exp2f((float)iv);
    return exp2f(__int_as_float(iv));
}

// ---------------- kernel 0: convert x to fp16 ----------------
__global__ void __launch_bounds__(256) conv_x_kernel(const float* __restrict__ xf)
{
    const size_t base = (size_t)blockIdx.x * 2048 + threadIdx.x;
    #pragma unroll
    for (int i = 0; i < 8; ++i) {
        size_t idx = base + i * 256;
        g_x[idx] = __float2half_rn(xf[idx]);
    }
}

// ---------------- fused dequant + GEMM: y = x @ (U@t).T + b ----------------
// CTA bid owns out-rows [bid*32, bid*32+32), all 512 batch rows.
// Warp w (0..7) owns batch rows [w*64, w*64+64).
__global__ void __launch_bounds__(256, 1) fused_gemm(
    const float4* __restrict__ U4,   // one float4 per W element, row-major [OUTF, INF]
    const float* __restrict__ q,
    const int* __restrict__ e,
    const float* __restrict__ bias,
    float* __restrict__ out)
{
    extern __shared__ char smem[];
    const uint32_t sb = smem_u32(smem);
    const int tid  = threadIdx.x;
    const int wid  = tid >> 5;
    const int lane = tid & 31;
    const int g    = lane >> 2;
    const int t    = lane & 3;
    const int bid  = blockIdx.x;
    const int n0   = bid * TN;

    const float sc = scale_from_exponent(e) * (1.0f / 7.0f);
    const float t0 = q[0] * sc, t1 = q[1] * sc, t2 = q[2] * sc, t3 = q[3] * sc;

    // ---- cp.async issuers ----
    // U chunk: 32 rows(n) x 64 cols(k) float4 -> linear smem (n*64+k)*16.
    auto issue_U = [&](int it) {
        const uint32_t Ust = sb + ((it & 1) ? OFF_U1 : OFF_U0);
        const size_t kbase = (size_t)it * KC;
        #pragma unroll
        for (int j = 0; j < 8; ++j) {
            int id = j * 256 + tid;            // 0..2047
            int n = id >> 6, k = id & 63;
            CP_ASYNC16(Ust + ((uint32_t)id << 4),
                       U4 + (size_t)(n0 + n) * INF + kbase + k);
        }
    };
    // A chunk (warp-private rows): warp w fills rows w*64..w*64+63, 8 x 16B units/row.
    // SW128 XOR swizzle: unit' = unit ^ (row & 7).
    auto issue_A = [&](int it) {
        const uint32_t Ast = sb + ((it & 1) ? OFF_A1 : OFF_A0);
        const size_t kbase = (size_t)it * KC;   // halves
        #pragma unroll
        for (int j = 0; j < 16; ++j) {
            int id = j * 32 + lane;             // 0..511 within warp
            int rl = id >> 3, u = id & 7;
            int r  = wid * 64 + rl;
            CP_ASYNC16(Ast + (uint32_t)(r * 128 + ((u ^ (r & 7)) << 4)),
                       g_x + (size_t)r * INF + kbase + u * 8);
        }
    };

    // ---- prologue: stages 0 and 1 ----
    issue_U(0); issue_A(0); CP_COMMIT();
    issue_U(1); issue_A(1); CP_COMMIT();

    float acc[4][4][4];
    #pragma unroll
    for (int i = 0; i < 4; ++i)
        #pragma unroll
        for (int j = 0; j < 4; ++j)
            #pragma unroll
            for (int k = 0; k < 4; ++k) acc[i][j][k] = 0.f;

    // ldmatrix lane base addresses (SW128 XOR; k-step applied as XOR of ks*32B)
    const int row_a = wid * 64 + (lane & 15);
    const uint32_t a_base = (uint32_t)(row_a * 128 + (((lane >> 4) ^ (row_a & 7)) << 4));
    const int row_b = ((lane >> 4) << 3) + (lane & 7);
    const uint32_t b_base = (uint32_t)(row_b * 128 + ((((lane >> 3) & 1) ^ (row_b & 7)) << 4));

    #pragma unroll 1
    for (int it = 0; it < ITERS; ++it) {
        CP_WAIT(1);
        __syncthreads();                        // stage `it` (U+A) visible to all

        // ---- dequant: U(it) -> B fp16 (SW128 XOR layout), 8 elems/thread ----
        {
            const uint32_t Ust = sb + ((it & 1) ? OFF_U1 : OFF_U0);
            const uint32_t Bst = sb + OFF_B;
            #pragma unroll
            for (int j = 0; j < 8; ++j) {
                int id = j * 256 + tid;          // 0..2047
                int n = id >> 6, k = id & 63;
                float4 v;
                LDS_F32X4(v, Ust + ((uint32_t)id << 4));
                __half h = __float2half_rn(
                    fmaf(v.x, t0, fmaf(v.y, t1, fmaf(v.z, t2, v.w * t3))));
                uint32_t ba = Bst + (uint32_t)(n * 128 + (((k >> 3) ^ (n & 7)) << 4)
                                               + ((k & 7) << 1));
                STS_B16(ba, __half_as_ushort(h));
            }
        }
        __syncthreads();                        // B ready; U(it) slot free

        if (it + 2 < ITERS) issue_U(it + 2);    // refill freed U slot

        // ---- MMA: A(it) x B ----
        const uint32_t Ast = sb + ((it & 1) ? OFF_A1 : OFF_A0);
        const uint32_t Bst = sb + OFF_B;
        #pragma unroll
        for (int ks = 0; ks < 4; ++ks) {
            const uint32_t kx = (uint32_t)ks << 5;   // XOR k-offset (ks*2 units)
            uint32_t a[4][4], b[4][2];
            #pragma unroll
            for (int mt = 0; mt < 4; ++mt) {
                LDSM_X4(a[mt][0], a[mt][1], a[mt][2], a[mt][3],
                        Ast + ((a_base + (uint32_t)(mt * 2048)) ^ kx));
            }
            #pragma unroll
            for (int np = 0; np < 2; ++np) {
                LDSM_X4(b[2 * np][0], b[2 * np][1], b[2 * np + 1][0], b[2 * np + 1][1],
                        Bst + ((b_base + (uint32_t)(np * 2048)) ^ kx));
            }
            #pragma unroll
            for (int mt = 0; mt < 4; ++mt)
                #pragma unroll
                for (int nt = 0; nt < 4; ++nt)
                    MMA_F16(acc[mt][nt], a[mt], b[nt]);
        }

        if (it + 2 < ITERS) issue_A(it + 2);    // warp-private rows: no barrier needed
        CP_COMMIT();
    }

    // ---- epilogue: registers -> gmem with fused bias, float2 stores ----
    #pragma unroll
    for (int nt = 0; nt < 4; ++nt) {
        const int n = n0 + nt * 8 + 2 * t;
        const float b0 = bias[n], b1 = bias[n + 1];
        #pragma unroll
        for (int mt = 0; mt < 4; ++mt) {
            const int m = wid * 64 + mt * 16 + g;
            float2 lo = make_float2(acc[mt][nt][0] + b0, acc[mt][nt][1] + b1);
            float2 hi = make_float2(acc[mt][nt][2] + b0, acc[mt][nt][3] + b1);
            *reinterpret_cast<float2*>(out + (size_t)m * OUTF + n) = lo;
            *reinterpret_cast<float2*>(out + (size_t)(m + 8) * OUTF + n) = hi;
        }
    }
}

// ---------------- launch ----------------
extern "C" void kernel_launch(void* const* d_in, const int* in_sizes, int n_in,
                              void* d_out, int out_size)
{
    const float* x = (const float*)d_in[0];   // [512, 4096]
    const float* U = (const float*)d_in[1];   // [4096*4096, 4]
    const float* q = (const float*)d_in[2];   // [4]
    const float* b = (const float*)d_in[3];   // [4096]
    const int*   e = (const int*)d_in[4];     // exponent scalar

    cudaFuncSetAttribute(fused_gemm,
                         cudaFuncAttributeMaxDynamicSharedMemorySize, SMEM_BYTES);

    conv_x_kernel<<<1024, 256>>>(x);
    fused_gemm<<<NCTAS, 256, SMEM_BYTES>>>((const float4*)U, q, e, b, (float*)d_out);
}

// round 13
// speedup vs baseline: 7.1930x; 1.0263x over previous
#include <cuda_runtime.h>
#include <cuda_fp16.h>
#include <cstdint>

// Problem constants
#define BATCH 512
#define INF   4096
#define OUTF  4096

// Fused-dequant GEMM: CTA = 32 out-rows x 512 batch, K-chunk 64 W-elements.
#define KC 64
#define ITERS (INF / KC)          // 64
#define TN 32
#define NCTAS (OUTF / TN)         // 128

// smem layout (bytes): A stages 512 rows x 128B (SW128 XOR swizzle),
// U stages 32x64 float4 linear, B double-buffered 32x128B (SW128 XOR).
#define OFF_A0 0
#define OFF_A1 65536
#define OFF_U0 131072
#define OFF_U1 163840
#define OFF_B0 196608
#define OFF_B1 200704
#define SMEM_BYTES 204800

// Scratch (device global = sanctioned scratch)
__device__ __half g_x[(size_t)BATCH * INF];  // x in fp16 (4 MB)

// ---------------- PTX helpers (plain-sm_103 legal) ----------------
__device__ __forceinline__ uint32_t smem_u32(const void* p) {
    uint32_t a;
    asm("{ .reg .u64 t; cvta.to.shared.u64 t, %1; cvt.u32.u64 %0, t; }" : "=r"(a) : "l"(p));
    return a;
}

#define CP_ASYNC16(dst_smem, src_gmem) \
    asm volatile("cp.async.cg.shared.global [%0], [%1], 16;" \
                 :: "r"((uint32_t)(dst_smem)), "l"(src_gmem) : "memory")
#define CP_COMMIT() asm volatile("cp.async.commit_group;" ::: "memory")
#define CP_WAIT(n)  asm volatile("cp.async.wait_group %0;" :: "n"(n) : "memory")

#define LDSM_X4(r0, r1, r2, r3, addr) \
    asm volatile("ldmatrix.sync.aligned.m8n8.x4.shared.b16 {%0,%1,%2,%3}, [%4];" \
                 : "=r"(r0), "=r"(r1), "=r"(r2), "=r"(r3) : "r"(addr))

#define MMA_F16(d, a, b) \
    asm volatile( \
        "mma.sync.aligned.m16n8k16.row.col.f32.f16.f16.f32 " \
        "{%0,%1,%2,%3}, {%4,%5,%6,%7}, {%8,%9}, {%0,%1,%2,%3};" \
        : "+f"((d)[0]), "+f"((d)[1]), "+f"((d)[2]), "+f"((d)[3]) \
        : "r"((a)[0]), "r"((a)[1]), "r"((a)[2]), "r"((a)[3]), \
          "r"((b)[0]), "r"((b)[1]))

#define LDS_F32X4(v, addr) \
    asm volatile("ld.shared.v4.f32 {%0,%1,%2,%3}, [%4];" \
                 : "=f"((v).x), "=f"((v).y), "=f"((v).z), "=f"((v).w) : "r"(addr))
#define STS_B16(addr, h) \
    asm volatile("st.shared.b16 [%0], %1;" :: "r"(addr), "h"(h) : "memory")

__device__ __forceinline__ float scale_from_exponent(const int* e) {
    int iv = *e;
    if (iv > -1000000 && iv < 1000000) return exp2f((float)iv);
    return exp2f(__int_as_float(iv));
}

// ---------------- kernel 0: convert x to fp16 ----------------
__global__ void __launch_bounds__(256) conv_x_kernel(const float* __restrict__ xf)
{
    const size_t base = (size_t)blockIdx.x * 2048 + threadIdx.x;
    #pragma unroll
    for (int i = 0; i < 8; ++i) {
        size_t idx = base + i * 256;
        g_x[idx] = __float2half_rn(xf[idx]);
    }
}

// ---------------- fused dequant + GEMM: y = x @ (U@t).T + b ----------------
// CTA bid owns out-rows [bid*32, bid*32+32), all 512 batch rows.
// Warp w (0..7) owns batch rows [w*64, w*64+64).
__global__ void __launch_bounds__(256, 1) fused_gemm(
    const float4* __restrict__ U4,   // one float4 per W element, row-major [OUTF, INF]
    const float* __restrict__ q,
    const int* __restrict__ e,
    const float* __restrict__ bias,
    float* __restrict__ out)
{
    extern __shared__ char smem[];
    const uint32_t sb = smem_u32(smem);
    const int tid  = threadIdx.x;
    const int wid  = tid >> 5;
    const int lane = tid & 31;
    const int g    = lane >> 2;
    const int t    = lane & 3;
    const int bid  = blockIdx.x;
    const int n0   = bid * TN;

    const float sc = scale_from_exponent(e) * (1.0f / 7.0f);
    const float t0 = q[0] * sc, t1 = q[1] * sc, t2 = q[2] * sc, t3 = q[3] * sc;

    // ---- cp.async issuers ----
    auto issue_U = [&](int it) {
        const uint32_t Ust = sb + ((it & 1) ? OFF_U1 : OFF_U0);
        const size_t kbase = (size_t)it * KC;
        #pragma unroll
        for (int j = 0; j < 8; ++j) {
            int id = j * 256 + tid;            // 0..2047
            int n = id >> 6, k = id & 63;
            CP_ASYNC16(Ust + ((uint32_t)id << 4),
                       U4 + (size_t)(n0 + n) * INF + kbase + k);
        }
    };
    // A chunk (warp-private rows): warp w fills rows w*64..w*64+63.
    auto issue_A = [&](int it) {
        const uint32_t Ast = sb + ((it & 1) ? OFF_A1 : OFF_A0);
        const size_t kbase = (size_t)it * KC;   // halves
        #pragma unroll
        for (int j = 0; j < 16; ++j) {
            int id = j * 32 + lane;             // 0..511 within warp
            int rl = id >> 3, u = id & 7;
            int r  = wid * 64 + rl;
            CP_ASYNC16(Ast + (uint32_t)(r * 128 + ((u ^ (r & 7)) << 4)),
                       g_x + (size_t)r * INF + kbase + u * 8);
        }
    };
    // dequant STS address for element id (n = id>>6, k = id&63) into B slot base
    auto b_sts_addr = [&](uint32_t Bst, int id) -> uint32_t {
        int n = id >> 6, k = id & 63;
        return Bst + (uint32_t)(n * 128 + (((k >> 3) ^ (n & 7)) << 4) + ((k & 7) << 1));
    };

    // ---- prologue: stages 0,1 with SPLIT commit groups (U then A) ----
    issue_U(0); CP_COMMIT();
    issue_A(0); CP_COMMIT();
    issue_U(1); CP_COMMIT();
    issue_A(1); CP_COMMIT();

    CP_WAIT(3);                                  // U(0) done
    __syncthreads();
    {   // dequant chunk 0 -> B0 (plain, pre-loop)
        const uint32_t Ust = sb + OFF_U0;
        const uint32_t Bst = sb + OFF_B0;
        #pragma unroll
        for (int j = 0; j < 8; ++j) {
            int id = j * 256 + tid;
            float4 v;
            LDS_F32X4(v, Ust + ((uint32_t)id << 4));
            __half h = __float2half_rn(fmaf(v.x, t0, fmaf(v.y, t1, fmaf(v.z, t2, v.w * t3))));
            STS_B16(b_sts_addr(Bst, id), __half_as_ushort(h));
        }
    }

    float acc[4][4][4];
    #pragma unroll
    for (int i = 0; i < 4; ++i)
        #pragma unroll
        for (int j = 0; j < 4; ++j)
            #pragma unroll
            for (int k = 0; k < 4; ++k) acc[i][j][k] = 0.f;

    // ldmatrix lane base addresses (SW128 XOR; k-step applied as XOR of ks*32B)
    const int row_a = wid * 64 + (lane & 15);
    const uint32_t a_base = (uint32_t)(row_a * 128 + (((lane >> 4) ^ (row_a & 7)) << 4));
    const int row_b = ((lane >> 4) << 3) + (lane & 7);
    const uint32_t b_base = (uint32_t)(row_b * 128 + ((((lane >> 3) & 1) ^ (row_b & 7)) << 4));

    #pragma unroll 1
    for (int it = 0; it < ITERS; ++it) {
        CP_WAIT(1);            // all but newest group done => A(it), U(it+1) complete
        __syncthreads();       // B[it&1] writes visible; MMA(it-1) done reading B[(it+1)&1]

        const bool have_next = (it + 1 < ITERS);
        const uint32_t Un = sb + (((it + 1) & 1) ? OFF_U1 : OFF_U0);
        const uint32_t Bn = sb + (((it + 1) & 1) ? OFF_B1 : OFF_B0);

        // load next chunk's U into registers (latency hidden under ks0 MMAs)
        float4 u[8];
        if (have_next) {
            #pragma unroll
            for (int j = 0; j < 8; ++j)
                LDS_F32X4(u[j], Un + ((uint32_t)(j * 256 + tid) << 4));
        }
        // refill freed U slot early (slot it&1; its last readers finished iter it-1)
        if (it + 2 < ITERS) issue_U(it + 2);
        CP_COMMIT();

        // ---- MMA(it) on B[it&1], interleaved with dequant STS into B[next] ----
        const uint32_t Ast = sb + ((it & 1) ? OFF_A1 : OFF_A0);
        const uint32_t Bst = sb + ((it & 1) ? OFF_B0 + (OFF_B1 - OFF_B0) : OFF_B0);
        const uint32_t Bcur = sb + ((it & 1) ? OFF_B1 : OFF_B0);
        (void)Bst;
        #pragma unroll
        for (int ks = 0; ks < 4; ++ks) {
            const uint32_t kx = (uint32_t)ks << 5;   // XOR k-offset
            uint32_t a[4][4], b[4][2];
            #pragma unroll
            for (int mt = 0; mt < 4; ++mt) {
                LDSM_X4(a[mt][0], a[mt][1], a[mt][2], a[mt][3],
                        Ast + ((a_base + (uint32_t)(mt * 2048)) ^ kx));
            }
            #pragma unroll
            for (int np = 0; np < 2; ++np) {
                LDSM_X4(b[2 * np][0], b[2 * np][1], b[2 * np + 1][0], b[2 * np + 1][1],
                        Bcur + ((b_base + (uint32_t)(np * 2048)) ^ kx));
            }
            #pragma unroll
            for (int mt = 0; mt < 4; ++mt)
                #pragma unroll
                for (int nt = 0; nt < 4; ++nt)
                    MMA_F16(acc[mt][nt], a[mt], b[nt]);

            // interleaved dequant: 2 elements per ks step (8 total per iter)
            if (have_next) {
                #pragma unroll
                for (int jj = 0; jj < 2; ++jj) {
                    int j = ks * 2 + jj;
                    __half h = __float2half_rn(
                        fmaf(u[j].x, t0, fmaf(u[j].y, t1, fmaf(u[j].z, t2, u[j].w * t3))));
                    STS_B16(b_sts_addr(Bn, j * 256 + tid), __half_as_ushort(h));
                }
            }
        }

        // refill A slot (warp-private rows; this warp's LDSM reads are done)
        if (it + 2 < ITERS) issue_A(it + 2);
        CP_COMMIT();
    }

    // ---- epilogue: registers -> gmem with fused bias, float2 stores ----
    #pragma unroll
    for (int nt = 0; nt < 4; ++nt) {
        const int n = n0 + nt * 8 + 2 * t;
        const float b0 = bias[n], b1 = bias[n + 1];
        #pragma unroll
        for (int mt = 0; mt < 4; ++mt) {
            const int m = wid * 64 + mt * 16 + g;
            float2 lo = make_float2(acc[mt][nt][0] + b0, acc[mt][nt][1] + b1);
            float2 hi = make_float2(acc[mt][nt][2] + b0, acc[mt][nt][3] + b1);
            *reinterpret_cast<float2*>(out + (size_t)m * OUTF + n) = lo;
            *reinterpret_cast<float2*>(out + (size_t)(m + 8) * OUTF + n) = hi;
        }
    }
}

// ---------------- launch ----------------
extern "C" void kernel_launch(void* const* d_in, const int* in_sizes, int n_in,
                              void* d_out, int out_size)
{
    const float* x = (const float*)d_in[0];   // [512, 4096]
    const float* U = (const float*)d_in[1];   // [4096*4096, 4]
    const float* q = (const float*)d_in[2];   // [4]
    const float* b = (const float*)d_in[3];   // [4096]
    const int*   e = (const int*)d_in[4];     // exponent scalar

    cudaFuncSetAttribute(fused_gemm,
                         cudaFuncAttributeMaxDynamicSharedMemorySize, SMEM_BYTES);

    conv_x_kernel<<<1024, 256>>>(x);
    fused_gemm<<<NCTAS, 256, SMEM_BYTES>>>((const float4*)U, q, e, b, (float*)d_out);
}